// round 2
// baseline (speedup 1.0000x reference)
#include <cuda_runtime.h>
#include <math.h>
#include <stdint.h>

// Problem constants (fixed by the dataset)
#define T_TOK   1024
#define D_DIM   2048
#define DFF_DIM 1024
#define E_EXP   16
#define K_TOP   6
#define P_PAIR  (T_TOK * K_TOP)          // 6144 token-expert pairs
#define BM      64
#define BN      64
#define BK      16
#define P_PAD   (P_PAIR + E_EXP * BM)    // 7168: worst-case padded rows
#define MAX_TILES (P_PAD / BM)           // 112

// ---- scratch (static device globals; no allocation anywhere) ----
__device__ int   g_rows[P_PAD];          // token index per padded slot (-1 = pad)
__device__ float g_wts [P_PAD];          // routing weight per padded slot
__device__ int   g_cnt [E_EXP];
__device__ int   g_cur [E_EXP];
__device__ int   g_basepad[E_EXP];
__device__ int   g_tile_e[MAX_TILES];
__device__ int   g_ntiles;
__device__ int   g_sel64;                // 1 if selected_experts is int64 on device
__device__ float g_H[(size_t)P_PAD * DFF_DIM];   // SwiGLU activations, ~28 MB

// ---------------- dtype detection for selected_experts ----------------
// Reads only the first 8KB of the buffer (safe under either int32 or int64
// layout). Int64 data: every (lo,hi) pair has hi==0 && 0<=lo<16. Int32 data
// viewed as pairs fails this almost surely (hi is a random value in 0..15,
// nonzero w.p. 15/16 per pair, 1024 pairs).
__global__ void detect_kernel(const void* sel) {
    __shared__ int bad;
    if (threadIdx.x == 0) bad = 0;
    __syncthreads();
    const int* w = (const int*)sel;
    for (int i = threadIdx.x; i < 1024; i += blockDim.x) {
        int lo = w[2 * i], hi = w[2 * i + 1];
        if (hi != 0 || (unsigned)lo >= E_EXP) atomicOr(&bad, 1);
    }
    __syncthreads();
    if (threadIdx.x == 0) g_sel64 = bad ? 0 : 1;
}

__device__ __forceinline__ int load_expert(const void* sel, int p) {
    int e;
    if (g_sel64) e = (int)((const long long*)sel)[p];
    else         e = ((const int*)sel)[p];
    return e & (E_EXP - 1);   // clamp: never produce a wild address
}

// ---------------- routing setup ----------------

__global__ void init_kernel(float* out, int out_n) {
    int i = blockIdx.x * blockDim.x + threadIdx.x;
    if (i < out_n) out[i] = 0.0f;
    if (i < P_PAD) g_rows[i] = -1;
    if (i < E_EXP) { g_cnt[i] = 0; g_cur[i] = 0; }
}

__global__ void count_kernel(const void* __restrict__ sel) {
    int p = blockIdx.x * blockDim.x + threadIdx.x;
    if (p < P_PAIR) atomicAdd(&g_cnt[load_expert(sel, p)], 1);
}

__global__ void setup_kernel() {
    int pos = 0;
    for (int e = 0; e < E_EXP; e++) {
        g_basepad[e] = pos;
        int tiles = (g_cnt[e] + BM - 1) / BM;
        for (int i = 0; i < tiles; i++) g_tile_e[pos / BM + i] = e;
        pos += tiles * BM;
    }
    g_ntiles = pos / BM;
}

__global__ void fill_kernel(const void* __restrict__ sel,
                            const float* __restrict__ rw) {
    int p = blockIdx.x * blockDim.x + threadIdx.x;
    if (p >= P_PAIR) return;
    int e = load_expert(sel, p);
    int slot = atomicAdd(&g_cur[e], 1);
    int idx = g_basepad[e] + slot;
    g_rows[idx] = p / K_TOP;
    g_wts[idx]  = rw[p];
}

// ---------------- GEMM 1: fused gate+up + SwiGLU ----------------
// H[slot, n] = silu(s0*(x[row]·w0[e,n,:])) * s1*(x[row]·w1[e,n,:])

__global__ __launch_bounds__(256) void gemm1_kernel(
    const float* __restrict__ x,  const float* __restrict__ w0,
    const float* __restrict__ w1, const float* __restrict__ s0,
    const float* __restrict__ s1)
{
    int tile = blockIdx.y;
    if (tile >= g_ntiles) return;
    int e  = g_tile_e[tile];
    int n0 = blockIdx.x * BN;

    __shared__ float sX [BK][BM + 4];
    __shared__ float sW0[BK][BN + 4];
    __shared__ float sW1[BK][BN + 4];

    int tid = threadIdx.x;
    int mi = tid >> 2, kv = tid & 3;       // loader mapping: 64 rows x 4 float4
    int row = g_rows[tile * BM + mi];
    bool rv = row >= 0;
    const float* xp  = x  + (size_t)(rv ? row : 0) * D_DIM + kv * 4;
    const float* w0p = w0 + ((size_t)e * DFF_DIM + n0 + mi) * D_DIM + kv * 4;
    const float* w1p = w1 + ((size_t)e * DFF_DIM + n0 + mi) * D_DIM + kv * 4;

    int ty = tid >> 4, tx = tid & 15;      // compute mapping: 16x16 thread grid, 4x4 each
    float ag[4][4] = {}, au[4][4] = {};

    for (int k0 = 0; k0 < D_DIM; k0 += BK) {
        float4 xv = rv ? *(const float4*)(xp + k0) : make_float4(0.f, 0.f, 0.f, 0.f);
        float4 av = *(const float4*)(w0p + k0);
        float4 bv = *(const float4*)(w1p + k0);
        __syncthreads();
        sX [kv*4+0][mi] = xv.x; sX [kv*4+1][mi] = xv.y; sX [kv*4+2][mi] = xv.z; sX [kv*4+3][mi] = xv.w;
        sW0[kv*4+0][mi] = av.x; sW0[kv*4+1][mi] = av.y; sW0[kv*4+2][mi] = av.z; sW0[kv*4+3][mi] = av.w;
        sW1[kv*4+0][mi] = bv.x; sW1[kv*4+1][mi] = bv.y; sW1[kv*4+2][mi] = bv.z; sW1[kv*4+3][mi] = bv.w;
        __syncthreads();
        #pragma unroll
        for (int kk = 0; kk < BK; kk++) {
            float4 a4  = *(const float4*)&sX [kk][ty * 4];
            float4 b04 = *(const float4*)&sW0[kk][tx * 4];
            float4 b14 = *(const float4*)&sW1[kk][tx * 4];
            float a [4] = {a4.x,  a4.y,  a4.z,  a4.w};
            float b0[4] = {b04.x, b04.y, b04.z, b04.w};
            float b1[4] = {b14.x, b14.y, b14.z, b14.w};
            #pragma unroll
            for (int i = 0; i < 4; i++)
                #pragma unroll
                for (int j = 0; j < 4; j++) {
                    ag[i][j] += a[i] * b0[j];
                    au[i][j] += a[i] * b1[j];
                }
        }
    }

    float s0e = s0[e], s1e = s1[e];
    float* hp = g_H + (size_t)(tile * BM) * DFF_DIM;
    #pragma unroll
    for (int i = 0; i < 4; i++)
        #pragma unroll
        for (int j = 0; j < 4; j++) {
            float g = ag[i][j] * s0e;
            float u = au[i][j] * s1e;
            float h = (g / (1.0f + expf(-g))) * u;       // silu(g) * u
            hp[(size_t)(ty * 4 + i) * DFF_DIM + n0 + tx * 4 + j] = h;
        }
}

// ---------------- GEMM 2: down projection + weighted scatter ----------------
// out[t, n] += wt * s2[e] * (H[slot,:] · w2[e, n, :])

__global__ __launch_bounds__(256) void gemm2_kernel(
    const float* __restrict__ w2, const float* __restrict__ s2,
    float* __restrict__ out)
{
    int tile = blockIdx.y;
    if (tile >= g_ntiles) return;
    int e  = g_tile_e[tile];
    int n0 = blockIdx.x * BN;

    __shared__ float sA[BK][BM + 4];
    __shared__ float sB[BK][BN + 4];

    int tid = threadIdx.x;
    int mi = tid >> 2, kv = tid & 3;
    const float* ap = g_H + (size_t)(tile * BM + mi) * DFF_DIM + kv * 4;
    const float* bp = w2  + ((size_t)e * D_DIM + n0 + mi) * DFF_DIM + kv * 4;

    int ty = tid >> 4, tx = tid & 15;
    float acc[4][4] = {};

    for (int k0 = 0; k0 < DFF_DIM; k0 += BK) {
        float4 av = *(const float4*)(ap + k0);
        float4 bv = *(const float4*)(bp + k0);
        __syncthreads();
        sA[kv*4+0][mi] = av.x; sA[kv*4+1][mi] = av.y; sA[kv*4+2][mi] = av.z; sA[kv*4+3][mi] = av.w;
        sB[kv*4+0][mi] = bv.x; sB[kv*4+1][mi] = bv.y; sB[kv*4+2][mi] = bv.z; sB[kv*4+3][mi] = bv.w;
        __syncthreads();
        #pragma unroll
        for (int kk = 0; kk < BK; kk++) {
            float4 a4 = *(const float4*)&sA[kk][ty * 4];
            float4 b4 = *(const float4*)&sB[kk][tx * 4];
            float a[4] = {a4.x, a4.y, a4.z, a4.w};
            float b[4] = {b4.x, b4.y, b4.z, b4.w};
            #pragma unroll
            for (int i = 0; i < 4; i++)
                #pragma unroll
                for (int j = 0; j < 4; j++)
                    acc[i][j] += a[i] * b[j];
        }
    }

    float s2e = s2[e];
    #pragma unroll
    for (int i = 0; i < 4; i++) {
        int slot = tile * BM + ty * 4 + i;
        int r = g_rows[slot];
        if (r < 0) continue;
        float wt = g_wts[slot] * s2e;
        #pragma unroll
        for (int j = 0; j < 4; j++)
            atomicAdd(&out[(size_t)r * D_DIM + n0 + tx * 4 + j], acc[i][j] * wt);
    }
}

// ---------------- launch ----------------

extern "C" void kernel_launch(void* const* d_in, const int* in_sizes, int n_in,
                              void* d_out, int out_size) {
    const float* x   = (const float*)d_in[0];
    const float* w0  = (const float*)d_in[1];
    const float* w1  = (const float*)d_in[2];
    const float* w2  = (const float*)d_in[3];
    const float* s0  = (const float*)d_in[4];
    const float* s1  = (const float*)d_in[5];
    const float* s2  = (const float*)d_in[6];
    const void*  sel = d_in[7];
    const float* rw  = (const float*)d_in[8];
    float* out = (float*)d_out;

    detect_kernel<<<1, 256>>>(sel);
    init_kernel<<<(out_size + 255) / 256, 256>>>(out, out_size);
    count_kernel<<<(P_PAIR + 255) / 256, 256>>>(sel);
    setup_kernel<<<1, 1>>>();
    fill_kernel<<<(P_PAIR + 255) / 256, 256>>>(sel, rw);
    gemm1_kernel<<<dim3(DFF_DIM / BN, MAX_TILES), 256>>>(x, w0, w1, s0, s1);
    gemm2_kernel<<<dim3(D_DIM / BN, MAX_TILES), 256>>>(w2, s2, out);
}

// round 4
// speedup vs baseline: 1.9972x; 1.9972x over previous
#include <cuda_runtime.h>
#include <cuda_bf16.h>
#include <math.h>
#include <stdint.h>

// ---------------- problem constants ----------------
#define T_TOK   1024
#define D_DIM   2048
#define DFF_DIM 1024
#define E_EXP   16
#define K_TOP   6
#define P_PAIR  (T_TOK * K_TOP)          // 6144
#define BM      128
#define P_PAD   (P_PAIR + E_EXP * BM)    // 8192
#define MAX_TILES (P_PAD / BM)           // 64
#define KBLK    32

// smem: 4 bf16 planes (Ahi, Alo, Bhi, Blo), 128 rows x 40 bf16 (80B stride)
#define ROWSTRIDE 80
#define PLANE     10240                  // 128 * 80
#define STAGE     40960                  // 4 planes
#define SMEM_BYTES (2 * STAGE)           // 81920, double buffered

// ---------------- static device scratch ----------------
__device__ int   g_rows[P_PAD];
__device__ int   g_slot[P_PAIR];
__device__ int   g_cnt [E_EXP];
__device__ int   g_cur [E_EXP];
__device__ int   g_basepad[E_EXP];
__device__ int   g_tile_e[MAX_TILES];
__device__ int   g_ntiles;
__device__ int   g_sel64;
__device__ __nv_bfloat16 g_Hhi[(size_t)P_PAD * DFF_DIM];   // 16 MB
__device__ __nv_bfloat16 g_Hlo[(size_t)P_PAD * DFF_DIM];   // 16 MB
__device__ float         g_Y  [(size_t)P_PAD * D_DIM];     // 64 MB

// ---------------- helpers ----------------
__device__ __forceinline__ uint32_t smem_u32(const void* p) {
    uint32_t a;
    asm("{ .reg .u64 t; cvta.to.shared.u64 t, %1; cvt.u32.u64 %0, t; }" : "=r"(a) : "l"(p));
    return a;
}

#define LDSM4(r, addr)                                                        \
    asm volatile("ldmatrix.sync.aligned.m8n8.x4.shared.b16 {%0,%1,%2,%3}, [%4];" \
        : "=r"((r)[0]), "=r"((r)[1]), "=r"((r)[2]), "=r"((r)[3]) : "r"(addr))

#define MMA(c, a, b0, b1)                                                     \
    asm volatile("mma.sync.aligned.m16n8k16.row.col.f32.bf16.bf16.f32 "       \
        "{%0,%1,%2,%3}, {%4,%5,%6,%7}, {%8,%9}, {%0,%1,%2,%3};"               \
        : "+f"((c)[0]), "+f"((c)[1]), "+f"((c)[2]), "+f"((c)[3])              \
        : "r"((a)[0]), "r"((a)[1]), "r"((a)[2]), "r"((a)[3]), "r"(b0), "r"(b1))

// 8 fp32 -> 8 bf16 hi (uint4) + 8 bf16 lo (uint4); error-free split
__device__ __forceinline__ void cvt8(float4 a, float4 b, uint4& hh, uint4& ll) {
    float f[8] = {a.x, a.y, a.z, a.w, b.x, b.y, b.z, b.w};
    uint32_t h[8], l[8];
    #pragma unroll
    for (int i = 0; i < 8; i++) {
        __nv_bfloat16 bh = __float2bfloat16(f[i]);
        __nv_bfloat16 bl = __float2bfloat16(f[i] - __bfloat162float(bh));
        h[i] = (uint32_t)__bfloat16_as_ushort(bh);
        l[i] = (uint32_t)__bfloat16_as_ushort(bl);
    }
    hh = make_uint4(h[0] | (h[1] << 16), h[2] | (h[3] << 16),
                    h[4] | (h[5] << 16), h[6] | (h[7] << 16));
    ll = make_uint4(l[0] | (l[1] << 16), l[2] | (l[3] << 16),
                    l[4] | (l[5] << 16), l[6] | (l[7] << 16));
}

// ---------------- dtype detection (int64 vs int32 selected_experts) ----------------
__global__ void detect_kernel(const void* sel) {
    __shared__ int bad;
    if (threadIdx.x == 0) bad = 0;
    __syncthreads();
    const int* w = (const int*)sel;
    for (int i = threadIdx.x; i < 1024; i += blockDim.x) {
        int lo = w[2 * i], hi = w[2 * i + 1];
        if (hi != 0 || (unsigned)lo >= E_EXP) atomicOr(&bad, 1);
    }
    __syncthreads();
    if (threadIdx.x == 0) g_sel64 = bad ? 0 : 1;
}
__device__ __forceinline__ int load_expert(const void* sel, int p) {
    int e = g_sel64 ? (int)((const long long*)sel)[p] : ((const int*)sel)[p];
    return e & (E_EXP - 1);
}

// ---------------- routing ----------------
__global__ void init_kernel() {
    int i = blockIdx.x * blockDim.x + threadIdx.x;
    if (i < P_PAD) g_rows[i] = -1;
    if (i < E_EXP) { g_cnt[i] = 0; g_cur[i] = 0; }
}
__global__ void count_kernel(const void* __restrict__ sel) {
    int p = blockIdx.x * blockDim.x + threadIdx.x;
    if (p < P_PAIR) atomicAdd(&g_cnt[load_expert(sel, p)], 1);
}
__global__ void setup_kernel() {
    int pos = 0;
    for (int e = 0; e < E_EXP; e++) {
        g_basepad[e] = pos;
        int tiles = (g_cnt[e] + BM - 1) / BM;
        for (int i = 0; i < tiles; i++) g_tile_e[pos / BM + i] = e;
        pos += tiles * BM;
    }
    g_ntiles = pos / BM;
}
__global__ void fill_kernel(const void* __restrict__ sel) {
    int p = blockIdx.x * blockDim.x + threadIdx.x;
    if (p >= P_PAIR) return;
    int e = load_expert(sel, p);
    int idx = g_basepad[e] + atomicAdd(&g_cur[e], 1);
    g_rows[idx] = p / K_TOP;
    g_slot[p] = idx;
}

// ---------------- GEMM1: x @ [w0|w1 interleaved]^T -> SwiGLU -> H ----------------
// CTA: 128 rows x 128 N (= 64 dff cols, gate/up interleaved: n even=gate, odd=up)
__global__ void __launch_bounds__(256) gemm1_mma(
    const float* __restrict__ x,  const float* __restrict__ w0,
    const float* __restrict__ w1, const float* __restrict__ s0,
    const float* __restrict__ s1)
{
    int tile = blockIdx.y;
    if (tile >= g_ntiles) return;
    int e  = g_tile_e[tile];
    int bx = blockIdx.x;                 // 64-wide dff block

    extern __shared__ char smem[];
    uint32_t sb = smem_u32(smem);
    int tid = threadIdx.x, lane = tid & 31, wid = tid >> 5;
    int wr = wid >> 2, wc = wid & 3;

    // ---- fill-side per-thread pointers: thread covers row fr, k-half fh ----
    int fr = tid >> 1, fh = tid & 1;
    int grow = g_rows[tile * BM + fr];
    const float* axp = (grow >= 0) ? x + (size_t)grow * D_DIM + fh * 16 : (const float*)0;
    int dffcol = bx * 64 + (fr >> 1);
    const float* bwp = ((fr & 1) ? w1 : w0) + ((size_t)e * DFF_DIM + dffcol) * D_DIM + fh * 16;
    uint32_t stsOff = (uint32_t)(fr * ROWSTRIDE + fh * 32);

    // ---- ldmatrix per-lane offsets ----
    int li = lane & 7;
    uint32_t offA = (uint32_t)((wr * 64 + ((lane >> 3) & 1) * 8 + li) * ROWSTRIDE
                               + ((lane >> 4) & 1) * 16);
    uint32_t offB = (uint32_t)((wc * 32 + ((lane >> 4) & 1) * 8 + li) * ROWSTRIDE
                               + ((lane >> 3) & 1) * 16);

    float acc[4][4][4];
    #pragma unroll
    for (int i = 0; i < 4; i++)
        #pragma unroll
        for (int j = 0; j < 4; j++)
            #pragma unroll
            for (int c = 0; c < 4; c++) acc[i][j][c] = 0.f;

    float4 rA[4], rB[4];
    auto ldg = [&](int k0) {
        #pragma unroll
        for (int q = 0; q < 4; q++) {
            rA[q] = axp ? *(const float4*)(axp + k0 + q * 4) : make_float4(0.f, 0.f, 0.f, 0.f);
            rB[q] = *(const float4*)(bwp + k0 + q * 4);
        }
    };
    auto sts = [&](int st) {
        char* base = smem + st * STAGE;
        uint4 hh0, ll0, hh1, ll1;
        cvt8(rA[0], rA[1], hh0, ll0); cvt8(rA[2], rA[3], hh1, ll1);
        *(uint4*)(base + 0 * PLANE + stsOff)      = hh0;
        *(uint4*)(base + 0 * PLANE + stsOff + 16) = hh1;
        *(uint4*)(base + 1 * PLANE + stsOff)      = ll0;
        *(uint4*)(base + 1 * PLANE + stsOff + 16) = ll1;
        cvt8(rB[0], rB[1], hh0, ll0); cvt8(rB[2], rB[3], hh1, ll1);
        *(uint4*)(base + 2 * PLANE + stsOff)      = hh0;
        *(uint4*)(base + 2 * PLANE + stsOff + 16) = hh1;
        *(uint4*)(base + 3 * PLANE + stsOff)      = ll0;
        *(uint4*)(base + 3 * PLANE + stsOff + 16) = ll1;
    };

    ldg(0); sts(0);
    __syncthreads();

    const int NKB = D_DIM / KBLK;   // 64
    for (int kb = 0; kb < NKB; kb++) {
        if (kb + 1 < NKB) ldg((kb + 1) * KBLK);
        uint32_t st = sb + (kb & 1) * STAGE;
        #pragma unroll
        for (int s = 0; s < 2; s++) {
            uint32_t Ah[4][4], Al[4][4], Bh[2][4], Bl[2][4];
            #pragma unroll
            for (int mi = 0; mi < 4; mi++) {
                LDSM4(Ah[mi], st + 0 * PLANE + offA + mi * 16 * ROWSTRIDE + s * 32);
                LDSM4(Al[mi], st + 1 * PLANE + offA + mi * 16 * ROWSTRIDE + s * 32);
            }
            #pragma unroll
            for (int nj = 0; nj < 2; nj++) {
                LDSM4(Bh[nj], st + 2 * PLANE + offB + nj * 16 * ROWSTRIDE + s * 32);
                LDSM4(Bl[nj], st + 3 * PLANE + offB + nj * 16 * ROWSTRIDE + s * 32);
            }
            #pragma unroll
            for (int mi = 0; mi < 4; mi++)
                #pragma unroll
                for (int nj = 0; nj < 2; nj++) {
                    MMA(acc[mi][nj*2],   Ah[mi], Bh[nj][0], Bh[nj][1]);
                    MMA(acc[mi][nj*2+1], Ah[mi], Bh[nj][2], Bh[nj][3]);
                    MMA(acc[mi][nj*2],   Ah[mi], Bl[nj][0], Bl[nj][1]);
                    MMA(acc[mi][nj*2+1], Ah[mi], Bl[nj][2], Bl[nj][3]);
                    MMA(acc[mi][nj*2],   Al[mi], Bh[nj][0], Bh[nj][1]);
                    MMA(acc[mi][nj*2+1], Al[mi], Bh[nj][2], Bh[nj][3]);
                }
        }
        if (kb + 1 < NKB) sts((kb + 1) & 1);
        __syncthreads();
    }

    // ---- epilogue: SwiGLU (gate=c even, up=c odd within thread), store H ----
    float s0e = s0[e], s1e = s1[e];
    #pragma unroll
    for (int mi = 0; mi < 4; mi++)
        #pragma unroll
        for (int nf = 0; nf < 4; nf++) {
            int r0  = tile * BM + wr * 64 + mi * 16 + (lane >> 2);
            int col = bx * 64 + wc * 16 + nf * 4 + (lane & 3);
            float g0 = acc[mi][nf][0] * s0e, u0 = acc[mi][nf][1] * s1e;
            float g8 = acc[mi][nf][2] * s0e, u8 = acc[mi][nf][3] * s1e;
            float h0 = (g0 / (1.f + __expf(-g0))) * u0;
            float h8 = (g8 / (1.f + __expf(-g8))) * u8;
            size_t o0 = (size_t)r0 * DFF_DIM + col;
            size_t o8 = o0 + (size_t)8 * DFF_DIM;
            __nv_bfloat16 b0 = __float2bfloat16(h0);
            __nv_bfloat16 b8 = __float2bfloat16(h8);
            g_Hhi[o0] = b0; g_Hlo[o0] = __float2bfloat16(h0 - __bfloat162float(b0));
            g_Hhi[o8] = b8; g_Hlo[o8] = __float2bfloat16(h8 - __bfloat162float(b8));
        }
}

// ---------------- GEMM2: H @ w2^T * s2 -> Y ----------------
// CTA: 128 rows x 128 d-cols
__global__ void __launch_bounds__(256) gemm2_mma(
    const float* __restrict__ w2, const float* __restrict__ s2)
{
    int tile = blockIdx.y;
    if (tile >= g_ntiles) return;
    int e  = g_tile_e[tile];
    int bx = blockIdx.x;                 // 128-wide d block

    extern __shared__ char smem[];
    uint32_t sb = smem_u32(smem);
    int tid = threadIdx.x, lane = tid & 31, wid = tid >> 5;
    int wr = wid >> 2, wc = wid & 3;

    int fr = tid >> 1, fh = tid & 1;
    const __nv_bfloat16* ahp = g_Hhi + (size_t)(tile * BM + fr) * DFF_DIM + fh * 16;
    const __nv_bfloat16* alp = g_Hlo + (size_t)(tile * BM + fr) * DFF_DIM + fh * 16;
    const float* bwp = w2 + ((size_t)e * D_DIM + bx * 128 + fr) * DFF_DIM + fh * 16;
    uint32_t stsOff = (uint32_t)(fr * ROWSTRIDE + fh * 32);

    int li = lane & 7;
    uint32_t offA = (uint32_t)((wr * 64 + ((lane >> 3) & 1) * 8 + li) * ROWSTRIDE
                               + ((lane >> 4) & 1) * 16);
    uint32_t offB = (uint32_t)((wc * 32 + ((lane >> 4) & 1) * 8 + li) * ROWSTRIDE
                               + ((lane >> 3) & 1) * 16);

    float acc[4][4][4];
    #pragma unroll
    for (int i = 0; i < 4; i++)
        #pragma unroll
        for (int j = 0; j < 4; j++)
            #pragma unroll
            for (int c = 0; c < 4; c++) acc[i][j][c] = 0.f;

    uint4 ha0, ha1, la0, la1;
    float4 rB[4];
    auto ldg = [&](int k0) {
        ha0 = *(const uint4*)(ahp + k0);     ha1 = *(const uint4*)(ahp + k0 + 8);
        la0 = *(const uint4*)(alp + k0);     la1 = *(const uint4*)(alp + k0 + 8);
        #pragma unroll
        for (int q = 0; q < 4; q++) rB[q] = *(const float4*)(bwp + k0 + q * 4);
    };
    auto sts = [&](int st) {
        char* base = smem + st * STAGE;
        *(uint4*)(base + 0 * PLANE + stsOff)      = ha0;
        *(uint4*)(base + 0 * PLANE + stsOff + 16) = ha1;
        *(uint4*)(base + 1 * PLANE + stsOff)      = la0;
        *(uint4*)(base + 1 * PLANE + stsOff + 16) = la1;
        uint4 hh0, ll0, hh1, ll1;
        cvt8(rB[0], rB[1], hh0, ll0); cvt8(rB[2], rB[3], hh1, ll1);
        *(uint4*)(base + 2 * PLANE + stsOff)      = hh0;
        *(uint4*)(base + 2 * PLANE + stsOff + 16) = hh1;
        *(uint4*)(base + 3 * PLANE + stsOff)      = ll0;
        *(uint4*)(base + 3 * PLANE + stsOff + 16) = ll1;
    };

    ldg(0); sts(0);
    __syncthreads();

    const int NKB = DFF_DIM / KBLK;   // 32
    for (int kb = 0; kb < NKB; kb++) {
        if (kb + 1 < NKB) ldg((kb + 1) * KBLK);
        uint32_t st = sb + (kb & 1) * STAGE;
        #pragma unroll
        for (int s = 0; s < 2; s++) {
            uint32_t Ah[4][4], Al[4][4], Bh[2][4], Bl[2][4];
            #pragma unroll
            for (int mi = 0; mi < 4; mi++) {
                LDSM4(Ah[mi], st + 0 * PLANE + offA + mi * 16 * ROWSTRIDE + s * 32);
                LDSM4(Al[mi], st + 1 * PLANE + offA + mi * 16 * ROWSTRIDE + s * 32);
            }
            #pragma unroll
            for (int nj = 0; nj < 2; nj++) {
                LDSM4(Bh[nj], st + 2 * PLANE + offB + nj * 16 * ROWSTRIDE + s * 32);
                LDSM4(Bl[nj], st + 3 * PLANE + offB + nj * 16 * ROWSTRIDE + s * 32);
            }
            #pragma unroll
            for (int mi = 0; mi < 4; mi++)
                #pragma unroll
                for (int nj = 0; nj < 2; nj++) {
                    MMA(acc[mi][nj*2],   Ah[mi], Bh[nj][0], Bh[nj][1]);
                    MMA(acc[mi][nj*2+1], Ah[mi], Bh[nj][2], Bh[nj][3]);
                    MMA(acc[mi][nj*2],   Ah[mi], Bl[nj][0], Bl[nj][1]);
                    MMA(acc[mi][nj*2+1], Ah[mi], Bl[nj][2], Bl[nj][3]);
                    MMA(acc[mi][nj*2],   Al[mi], Bh[nj][0], Bh[nj][1]);
                    MMA(acc[mi][nj*2+1], Al[mi], Bh[nj][2], Bh[nj][3]);
                }
        }
        if (kb + 1 < NKB) sts((kb + 1) & 1);
        __syncthreads();
    }

    float s2e = s2[e];
    #pragma unroll
    for (int mi = 0; mi < 4; mi++)
        #pragma unroll
        for (int nf = 0; nf < 4; nf++) {
            int r0  = tile * BM + wr * 64 + mi * 16 + (lane >> 2);
            int col = bx * 128 + wc * 32 + nf * 8 + 2 * (lane & 3);
            float2 v0 = make_float2(acc[mi][nf][0] * s2e, acc[mi][nf][1] * s2e);
            float2 v8 = make_float2(acc[mi][nf][2] * s2e, acc[mi][nf][3] * s2e);
            *(float2*)(g_Y + (size_t)r0 * D_DIM + col) = v0;
            *(float2*)(g_Y + (size_t)(r0 + 8) * D_DIM + col) = v8;
        }
}

// ---------------- final gather: out[t] = sum_k rw[t,k] * Y[slot(t,k)] ----------------
__global__ void gather_kernel(float* __restrict__ out, const float* __restrict__ rw) {
    int idx = blockIdx.x * blockDim.x + threadIdx.x;
    int t = idx >> 9;
    int q = (idx & 511) * 4;
    float4 acc = make_float4(0.f, 0.f, 0.f, 0.f);
    #pragma unroll
    for (int k = 0; k < K_TOP; k++) {
        int p = t * K_TOP + k;
        float w = rw[p];
        const float4 v = *(const float4*)(g_Y + (size_t)g_slot[p] * D_DIM + q);
        acc.x += w * v.x; acc.y += w * v.y; acc.z += w * v.z; acc.w += w * v.w;
    }
    *(float4*)(out + (size_t)t * D_DIM + q) = acc;
}

// ---------------- launch ----------------
extern "C" void kernel_launch(void* const* d_in, const int* in_sizes, int n_in,
                              void* d_out, int out_size) {
    const float* x   = (const float*)d_in[0];
    const float* w0  = (const float*)d_in[1];
    const float* w1  = (const float*)d_in[2];
    const float* w2  = (const float*)d_in[3];
    const float* s0  = (const float*)d_in[4];
    const float* s1  = (const float*)d_in[5];
    const float* s2  = (const float*)d_in[6];
    const void*  sel = d_in[7];
    const float* rw  = (const float*)d_in[8];
    float* out = (float*)d_out;

    cudaFuncSetAttribute(gemm1_mma, cudaFuncAttributeMaxDynamicSharedMemorySize, SMEM_BYTES);
    cudaFuncSetAttribute(gemm2_mma, cudaFuncAttributeMaxDynamicSharedMemorySize, SMEM_BYTES);

    detect_kernel<<<1, 256>>>(sel);
    init_kernel<<<(P_PAD + 255) / 256, 256>>>();
    count_kernel<<<(P_PAIR + 255) / 256, 256>>>(sel);
    setup_kernel<<<1, 1>>>();
    fill_kernel<<<(P_PAIR + 255) / 256, 256>>>(sel);
    gemm1_mma<<<dim3(DFF_DIM / 64, MAX_TILES), 256, SMEM_BYTES>>>(x, w0, w1, s0, s1);
    gemm2_mma<<<dim3(D_DIM / 128, MAX_TILES), 256, SMEM_BYTES>>>(w2, s2);
    gather_kernel<<<(T_TOK * 512) / 256, 256>>>(out, rw);
}